// round 15
// baseline (speedup 1.0000x reference)
#include <cuda_runtime.h>
#include <cuda_bf16.h>
#include <math.h>

typedef unsigned int u32;
typedef unsigned long long u64;

#define NA   196416   // anchors per image
#define NP   21824    // positions per image
#define KSEL 300
#define NB   8
#define CMAX 2048     // candidate cap per image
#define GEX  8        // candidates per k_exact block
#define TPI  171      // GEMM tiles per image (170 x 128 pos + 1 x 64 pos)

__device__ u32 g_keys[NB * NA];        // approx sortable logit keys
__device__ u32 g_hist1[NB * 2048];
__device__ u32 g_hist2[NB * 2048];
__device__ u32 g_sel1[NB * 2];
__device__ u32 g_sel2[NB * 2];
__device__ u32 g_ccnt[NB];
__device__ u32 g_cand[NB * CMAX];      // candidate anchor indices (within image)
__device__ u64 g_eres[NB * CMAX];      // recomputed composite keys (key<<32 | ~idx)
__device__ int g_stage[NB * KSEL];
__device__ uint4 g_wbf4[65536 / 8];    // W bf16 [256 o][256 k]

__device__ __forceinline__ u32 fkey(float v) {
    u32 s = __float_as_uint(v);
    return (s & 0x80000000u) ? ~s : (s | 0x80000000u);
}
__device__ __forceinline__ u32 smem_u32(const void* p) {
    u32 a;
    asm("{ .reg .u64 t; cvta.to.shared.u64 t, %1; cvt.u32.u64 %0, t; }" : "=r"(a) : "l"(p));
    return a;
}
__device__ __forceinline__ void ldsm_x4(u32 addr, u32* r) {
    asm volatile("ldmatrix.sync.aligned.m8n8.x4.shared.b16 {%0,%1,%2,%3}, [%4];"
        : "=r"(r[0]), "=r"(r[1]), "=r"(r[2]), "=r"(r[3]) : "r"(addr));
}
__device__ __forceinline__ void ldsm_x4t(u32 addr, u32* r) {
    asm volatile("ldmatrix.sync.aligned.m8n8.x4.trans.shared.b16 {%0,%1,%2,%3}, [%4];"
        : "=r"(r[0]), "=r"(r[1]), "=r"(r[2]), "=r"(r[3]) : "r"(addr));
}
__device__ __forceinline__ void mma_bf16(float* d, const u32* a, const u32* b) {
    asm volatile(
        "mma.sync.aligned.m16n8k16.row.col.f32.bf16.bf16.f32 "
        "{%0,%1,%2,%3}, {%4,%5,%6,%7}, {%8,%9}, {%0,%1,%2,%3};"
        : "+f"(d[0]), "+f"(d[1]), "+f"(d[2]), "+f"(d[3])
        : "r"(a[0]), "r"(a[1]), "r"(a[2]), "r"(a[3]), "r"(b[0]), "r"(b[1]));
}
__device__ __forceinline__ void cp16(u32 dst, const void* src) {
    asm volatile("cp.async.cg.shared.global [%0], [%1], 16;" :: "r"(dst), "l"(src) : "memory");
}
#define CP_COMMIT() asm volatile("cp.async.commit_group;" ::: "memory")
#define CP_WAIT0()  asm volatile("cp.async.wait_group 0;" ::: "memory")

// ---------------------------------------------------------------------------
// Prep: W -> bf16 [256 o][256 k]
// ---------------------------------------------------------------------------
__global__ void __launch_bounds__(256) k_wprep(const float* __restrict__ w_pre)
{
    const int i = blockIdx.x * 256 + threadIdx.x;
    ((__nv_bfloat16*)g_wbf4)[i] = __float2bfloat16(w_pre[i]);
}

// ---------------------------------------------------------------------------
// K1: single-product bf16 mma.sync GEMM 256x256 conv + ReLU + fp32 proj.
// Block: M=256 x N=128 positions, 8 warps (4 m x 2 n), K chunks of 64, dbuf.
// smem: W [buf][256 o][144B rows], X [buf][64 k][272B rows].
// ---------------------------------------------------------------------------
#define SW_BUF  36864
#define SX_BASE 73728
#define SX_BUF  17408
#define SMO_WPROJ 139264
#define SMO_BPRE  148480
#define SMO_BPROJ 149504
#define SM_TOT    149568

__global__ void __launch_bounds__(256, 1) k_logits(
    const float* __restrict__ f0, const float* __restrict__ f1,
    const float* __restrict__ f2, const float* __restrict__ f3,
    const float* __restrict__ f4,
    const float* __restrict__ b_pre_g,
    const float* __restrict__ w_proj_g, const float* __restrict__ b_proj_g,
    float* __restrict__ out_lg)
{
    extern __shared__ unsigned char sm[];
    const u32 smb = smem_u32(sm);
    float* pre_s   = (float*)sm;                    // epilogue reuse [256 o][136]
    float* wproj_s = (float*)(sm + SMO_WPROJ);
    float* bpre_s  = (float*)(sm + SMO_BPRE);
    float* bproj_s = (float*)(sm + SMO_BPROJ);

    const int tid = threadIdx.x;
    const int wid = tid >> 5;
    const int lane = tid & 31;
    const int mw = wid >> 1;     // 0..3 (M group of 64)
    const int nw = wid & 1;      // 0..1 (N group of 64)

    // fold topk zeroing into spare blocks
    if (blockIdx.x < 64)        g_hist1[blockIdx.x * 256 + tid] = 0;
    else if (blockIdx.x < 128)  g_hist2[(blockIdx.x - 64) * 256 + tid] = 0;
    else if (blockIdx.x == 128 && tid < NB) g_ccnt[tid] = 0;

    for (int i = tid; i < 2304; i += 256) wproj_s[i] = w_proj_g[i];
    bpre_s[tid] = b_pre_g[tid];
    if (tid < 9) bproj_s[tid] = b_proj_g[tid];

    // block decode
    const int img = blockIdx.x / TPI;
    const int t = blockIdx.x - img * TPI;
    const float* F; int HW, posoff, pt, Ntile;
    if (t < 128)      { F = f0; HW = 16384; posoff = 0;     pt = t;       Ntile = 128; }
    else if (t < 160) { F = f1; HW = 4096;  posoff = 16384; pt = t - 128; Ntile = 128; }
    else if (t < 168) { F = f2; HW = 1024;  posoff = 20480; pt = t - 160; Ntile = 128; }
    else if (t < 170) { F = f3; HW = 256;   posoff = 21504; pt = t - 168; Ntile = 128; }
    else              { F = f4; HW = 64;    posoff = 21760; pt = 0;       Ntile = 64;  }
    const float* Xg = F + (size_t)img * 256 * HW + (size_t)pt * 128;
    const int pmask = (Ntile == 128) ? 127 : 63;

    const __nv_bfloat16* gW = (const __nv_bfloat16*)g_wbf4;

    // per-lane ldmatrix address components
    const u32 aoff = (u32)((mw * 64 + (lane & 15)) * 144 + ((lane >> 4) << 4));
    const u32 boff = (u32)(((lane & 7) + (lane & 8)) * 272 + ((nw * 64 + ((lane >> 4) << 3)) << 1));

    // X staging: thread -> k row (tid>>2: 0..63), p block (tid&3)*32
    const int xk = tid >> 2;
    const int xp4 = (tid & 3) * 32;

    float acc[4][8][4];
    #pragma unroll
    for (int mi = 0; mi < 4; mi++)
        #pragma unroll
        for (int nf = 0; nf < 8; nf++)
            #pragma unroll
            for (int q = 0; q < 4; q++) acc[mi][nf][q] = 0.f;

    float4 xv[8];

    auto issueW = [&](int c, int buf) {
        #pragma unroll
        for (int i = 0; i < 8; i++) {
            const int idx = tid + i * 256;
            const int o = idx >> 3, j = idx & 7;
            const u32 dst = smb + (u32)(buf * SW_BUF + o * 144 + j * 16);
            cp16(dst, gW + o * 256 + c * 64 + j * 8);
        }
        CP_COMMIT();
    };
    auto loadX = [&](int c) {
        #pragma unroll
        for (int i = 0; i < 8; i++) {
            const int p = (xp4 + 4 * i) & pmask;
            xv[i] = *(const float4*)(Xg + (size_t)(c * 64 + xk) * HW + p);
        }
    };
    auto stsX = [&](int buf) {
        const u32 rb = smb + (u32)(SX_BASE + buf * SX_BUF + xk * 272);
        #pragma unroll
        for (int i = 0; i < 8; i++) {
            const float4 v = xv[i];
            const u32 w0 = ((u32)__bfloat16_as_ushort(__float2bfloat16(v.y)) << 16)
                         | (u32)__bfloat16_as_ushort(__float2bfloat16(v.x));
            const u32 w1 = ((u32)__bfloat16_as_ushort(__float2bfloat16(v.w)) << 16)
                         | (u32)__bfloat16_as_ushort(__float2bfloat16(v.z));
            asm volatile("st.shared.v2.u32 [%0], {%1, %2};"
                         :: "r"(rb + (u32)((xp4 + 4 * i) * 2)), "r"(w0), "r"(w1) : "memory");
        }
    };

    issueW(0, 0);
    loadX(0);
    CP_WAIT0();
    __syncthreads();
    stsX(0);
    __syncthreads();

    for (int c = 0; c < 4; c++) {
        const int cur = c & 1, nxt = cur ^ 1;
        if (c < 3) { issueW(c + 1, nxt); loadX(c + 1); }

        #pragma unroll
        for (int k16 = 0; k16 < 4; k16++) {
            const u32 abase = smb + (u32)(cur * SW_BUF) + aoff + (u32)(k16 * 32);
            const u32 bbase = smb + (u32)(SX_BASE + cur * SX_BUF + k16 * 4352) + boff;
            u32 A[4][4], B[4][4];
            #pragma unroll
            for (int mi = 0; mi < 4; mi++) ldsm_x4(abase + mi * 2304, A[mi]);
            #pragma unroll
            for (int q = 0; q < 4; q++) ldsm_x4t(bbase + q * 32, B[q]);
            #pragma unroll
            for (int mi = 0; mi < 4; mi++)
                #pragma unroll
                for (int q = 0; q < 4; q++) {
                    mma_bf16(acc[mi][2 * q], A[mi], &B[q][0]);
                    mma_bf16(acc[mi][2 * q + 1], A[mi], &B[q][2]);
                }
        }

        if (c < 3) {
            CP_WAIT0();
            __syncthreads();
            stsX(nxt);
            __syncthreads();
        }
    }

    // epilogue: relu(acc + b_pre) -> pre_s[o][136]
    __syncthreads();
    #pragma unroll
    for (int mi = 0; mi < 4; mi++) {
        #pragma unroll
        for (int h = 0; h < 2; h++) {
            const int o = mw * 64 + mi * 16 + (lane >> 2) + 8 * h;
            const float bb = bpre_s[o];
            #pragma unroll
            for (int nf = 0; nf < 8; nf++) {
                const int n = nw * 64 + nf * 8 + 2 * (lane & 3);
                float2 v;
                v.x = fmaxf(acc[mi][nf][2 * h] + bb, 0.f);
                v.y = fmaxf(acc[mi][nf][2 * h + 1] + bb, 0.f);
                *(float2*)(pre_s + o * 136 + n) = v;
            }
        }
    }
    __syncthreads();

    // projection: thread (p, grp): grp0 -> a 0..4, grp1 -> a 5..8
    {
        const int p = tid & 127;
        const int grp = tid >> 7;
        if (p < Ntile) {
            const int a0 = grp ? 5 : 0;
            const int na = grp ? 4 : 5;
            float pa[5] = {0.f, 0.f, 0.f, 0.f, 0.f};
            #pragma unroll 4
            for (int o = 0; o < 256; o++) {
                const float v = pre_s[o * 136 + p];
                #pragma unroll
                for (int q = 0; q < 5; q++)
                    if (q < na) pa[q] = fmaf(wproj_s[(a0 + q) * 256 + o], v, pa[q]);
            }
            const size_t obase = (size_t)img * NA;
            const int ab = (posoff + pt * 128 + p) * 9;
            for (int q = 0; q < na; q++) {
                const float val = pa[q] + bproj_s[a0 + q];
                const int anch = ab + a0 + q;
                if (out_lg) out_lg[obase + anch] = val;
                g_keys[obase + anch] = fkey(val);
            }
        }
    }
}

// ---------------------------------------------------------------------------
// Top-k radix passes
// ---------------------------------------------------------------------------
__device__ __forceinline__ void hadd(u32* hist, u32 bin, bool valid, int lane) {
    u32 key = valid ? bin : 0xFFFFFFFFu;
    u32 m = __match_any_sync(0xFFFFFFFFu, key);
    if (valid && lane == (__ffs(m) - 1)) atomicAdd(&hist[bin], __popc(m));
}

__global__ void __launch_bounds__(256) k_hist1()
{
    __shared__ u32 hist[2048];
    const int t = threadIdx.x, img = blockIdx.y, chunk = blockIdx.x;
    const int lane = t & 31;
    for (int i = t; i < 2048; i += 256) hist[i] = 0;
    __syncthreads();
    const uint4* src = (const uint4*)(g_keys + img * NA) + chunk * 2046;
    for (int i = t; i < 2048; i += 256) {
        const bool v = i < 2046;
        uint4 x = v ? src[i] : make_uint4(0, 0, 0, 0);
        hadd(hist, x.x >> 21, v, lane);
        hadd(hist, x.y >> 21, v, lane);
        hadd(hist, x.z >> 21, v, lane);
        hadd(hist, x.w >> 21, v, lane);
    }
    __syncthreads();
    for (int i = t; i < 2048; i += 256)
        if (hist[i]) atomicAdd(&g_hist1[img * 2048 + i], hist[i]);
}

__global__ void __launch_bounds__(256) k_hist2()
{
    __shared__ u32 hist[2048];
    const int t = threadIdx.x, img = blockIdx.y, chunk = blockIdx.x;
    const int lane = t & 31;
    const u32 B1 = g_sel1[img * 2];
    for (int i = t; i < 2048; i += 256) hist[i] = 0;
    __syncthreads();
    const uint4* src = (const uint4*)(g_keys + img * NA) + chunk * 2046;
    for (int i = t; i < 2048; i += 256) {
        const bool v = i < 2046;
        uint4 x = v ? src[i] : make_uint4(0, 0, 0, 0);
        hadd(hist, (x.x >> 10) & 2047u, v && ((x.x >> 21) == B1), lane);
        hadd(hist, (x.y >> 10) & 2047u, v && ((x.y >> 21) == B1), lane);
        hadd(hist, (x.z >> 10) & 2047u, v && ((x.z >> 21) == B1), lane);
        hadd(hist, (x.w >> 10) & 2047u, v && ((x.w >> 21) == B1), lane);
    }
    __syncthreads();
    for (int i = t; i < 2048; i += 256)
        if (hist[i]) atomicAdd(&g_hist2[img * 2048 + i], hist[i]);
}

__global__ void __launch_bounds__(256) k_scan(int pass)
{
    __shared__ u32 h[2048];
    __shared__ u32 part[256], sc[256];
    __shared__ u32 res[2];
    const int t = threadIdx.x, img = blockIdx.x;
    const u32* H = (pass ? g_hist2 : g_hist1) + img * 2048;
    for (int i = t; i < 2048; i += 256) h[i] = H[i];
    __syncthreads();
    const u32 base = pass ? g_sel1[img * 2 + 1] : 0u;
    const u32 need = KSEL - base;
    u32 loc = 0;
    #pragma unroll
    for (int q = 0; q < 8; q++) loc += h[2047 - (t * 8 + q)];
    part[t] = loc; sc[t] = loc;
    __syncthreads();
    for (int off = 1; off < 256; off <<= 1) {
        u32 v = (t >= off) ? sc[t - off] : 0u;
        __syncthreads();
        sc[t] += v;
        __syncthreads();
    }
    const u32 A = sc[t] - part[t];
    if (A < need && A + part[t] >= need) {
        u32 cum = A;
        #pragma unroll
        for (int q = 0; q < 8; q++) {
            const u32 bin = 2047 - (t * 8 + q);
            const u32 hv = h[bin];
            if (cum + hv >= need) { res[0] = bin; res[1] = base + cum; break; }
            cum += hv;
        }
    }
    __syncthreads();
    if (t == 0) {
        u32* outsel = (pass ? g_sel2 : g_sel1) + img * 2;
        outsel[0] = res[0]; outsel[1] = res[1];
    }
}

// collect candidates: approx top-22 bits >= threshold bin - 64 (noise margin)
__global__ void __launch_bounds__(256) k_collect()
{
    const int t = threadIdx.x, img = blockIdx.y, chunk = blockIdx.x;
    const u32 hi22 = (g_sel1[img * 2] << 11) | g_sel2[img * 2];
    const u32 lo = (hi22 > 64) ? (hi22 - 64) : 0u;
    const uint4* src = (const uint4*)(g_keys + img * NA) + chunk * 2046;
    u32* cand = g_cand + (size_t)img * CMAX;
    for (int i = t; i < 2046; i += 256) {
        uint4 x = src[i];
        const u32 ib = (u32)((chunk * 2046 + i) * 4);
        u32 xs4[4] = {x.x, x.y, x.z, x.w};
        #pragma unroll
        for (int c = 0; c < 4; c++) {
            if ((xs4[c] >> 10) >= lo) {
                const u32 slot = atomicAdd(&g_ccnt[img], 1u);
                if (slot < CMAX) cand[slot] = ib + c;
            }
        }
    }
}

// ---------------------------------------------------------------------------
// k_exact: fp32 recompute replicating R4's JAX-matching arithmetic.
// ---------------------------------------------------------------------------
__global__ void __launch_bounds__(256) k_exact(
    const float* __restrict__ f0, const float* __restrict__ f1,
    const float* __restrict__ f2, const float* __restrict__ f3,
    const float* __restrict__ f4,
    const float* __restrict__ w_pre, const float* __restrict__ b_pre,
    const float* __restrict__ w_proj, const float* __restrict__ b_proj)
{
    __shared__ float xs[GEX][260];       // x channels per candidate; reused as pre
    __shared__ float wc[256][33];        // W chunk [o][32k], padded
    __shared__ int s_idx[GEX];

    const int tid = threadIdx.x;
    const int img = blockIdx.x >> 8;           // / 256
    const int grp = blockIdx.x & 255;
    u32 cnt = g_ccnt[img]; if (cnt > CMAX) cnt = CMAX;
    const int base = grp * GEX;
    u64* outk = g_eres + (size_t)img * CMAX;

    if ((u32)base >= cnt) {
        if (tid < GEX) outk[base + tid] = 0ull;
        return;
    }
    if (tid < GEX)
        s_idx[tid] = ((u32)(base + tid) < cnt) ? (int)g_cand[(size_t)img * CMAX + base + tid] : -1;
    __syncthreads();

    #pragma unroll 1
    for (int g = 0; g < GEX; g++) {
        const int idx = s_idx[g];
        float v = 0.f;
        if (idx >= 0) {
            const int pos = idx / 9;
            const float* F; int HW, off;
            if (pos < 16384)      { F = f0; HW = 16384; off = 0; }
            else if (pos < 20480) { F = f1; HW = 4096;  off = 16384; }
            else if (pos < 21504) { F = f2; HW = 1024;  off = 20480; }
            else if (pos < 21760) { F = f3; HW = 256;   off = 21504; }
            else                  { F = f4; HW = 64;    off = 21760; }
            v = F[((size_t)img * 256 + tid) * (size_t)HW + (pos - off)];
        }
        xs[g][tid] = v;
    }

    float acc_e[GEX], acc_o[GEX];
    #pragma unroll
    for (int g = 0; g < GEX; g++) { acc_e[g] = 0.f; acc_o[g] = 0.f; }

    for (int kc = 0; kc < 8; kc++) {
        __syncthreads();
        for (int i = tid; i < 8192; i += 256) {
            const int o = i >> 5, k = i & 31;
            wc[o][k] = w_pre[o * 256 + kc * 32 + k];
        }
        __syncthreads();
        const int kb = kc * 32;
        #pragma unroll 4
        for (int kk = 0; kk < 32; kk += 2) {
            const float we = wc[tid][kk];
            const float wo = wc[tid][kk + 1];
            #pragma unroll
            for (int g = 0; g < GEX; g++) {
                acc_e[g] = fmaf(we, xs[g][kb + kk], acc_e[g]);
                acc_o[g] = fmaf(wo, xs[g][kb + kk + 1], acc_o[g]);
            }
        }
    }
    __syncthreads();

    const float bb = b_pre[tid];
    #pragma unroll
    for (int g = 0; g < GEX; g++)
        xs[g][tid] = fmaxf(acc_e[g] + acc_o[g] + bb, 0.f);
    __syncthreads();

    if (tid < GEX) {
        const int idx = s_idx[tid];
        if (idx >= 0) {
            const int a = idx - (idx / 9) * 9;
            const float* wp = w_proj + a * 256;
            float lg = 0.f;
            #pragma unroll 8
            for (int o = 0; o < 256; o++)
                lg = fmaf(wp[o], xs[tid][o], lg);
            const float val = lg + b_proj[a];
            outk[base + tid] = ((u64)fkey(val) << 32) | (u64)(0xFFFFFFFFu - (u32)idx);
        } else {
            outk[base + tid] = 0ull;
        }
    }
}

// ---------------------------------------------------------------------------
// k_final: sort up to 2048 keys desc (key desc, idx asc), emit top-300
// ---------------------------------------------------------------------------
__global__ void __launch_bounds__(1024) k_final(float* __restrict__ out_ids)
{
    __shared__ u64 keys[CMAX];
    const int t = threadIdx.x, img = blockIdx.x;
    u32 cnt = g_ccnt[img];
    if (cnt > CMAX) cnt = CMAX;
    u32 m = 512; while (m < cnt) m <<= 1;
    for (u32 i = t; i < m; i += 1024)
        keys[i] = (i < cnt) ? g_eres[(size_t)img * CMAX + i] : 0ull;
    __syncthreads();
    for (u32 k = 2; k <= m; k <<= 1)
        for (u32 j = k >> 1; j > 0; j >>= 1) {
            for (u32 i = t; i < m; i += 1024) {
                const u32 ix = i ^ j;
                if (ix > i) {
                    const u64 a = keys[i], c = keys[ix];
                    const bool down = ((i & k) == 0);
                    if ((a < c) == down) { keys[i] = c; keys[ix] = a; }
                }
            }
            __syncthreads();
        }
    if (t < KSEL) {
        const u32 idx = 0xFFFFFFFFu - (u32)keys[t];
        const int sel = img * NA + (int)idx;
        g_stage[img * KSEL + t] = sel;
        if (out_ids) out_ids[img * KSEL + t] = (float)sel;
    }
}

// ---------------------------------------------------------------------------
// K3: gather selected features [2400, 256]
// ---------------------------------------------------------------------------
__global__ void __launch_bounds__(256) k_gather(
    const float* __restrict__ f0, const float* __restrict__ f1,
    const float* __restrict__ f2, const float* __restrict__ f3,
    const float* __restrict__ f4, float* __restrict__ out_f)
{
    const int j = blockIdx.x;
    const int id = g_stage[j];
    const int b = id / NA;
    const int p = id / 9 - b * NP;
    const float* F; int HW, off;
    if (p < 16384)      { F = f0; HW = 16384; off = 0; }
    else if (p < 20480) { F = f1; HW = 4096;  off = 16384; }
    else if (p < 21504) { F = f2; HW = 1024;  off = 20480; }
    else if (p < 21760) { F = f3; HW = 256;   off = 21504; }
    else                { F = f4; HW = 64;    off = 21760; }
    const int pos = p - off;
    const int c = threadIdx.x;
    out_f[(size_t)j * 256 + c] = F[((size_t)b * 256 + c) * (size_t)HW + pos];
}

// ---------------------------------------------------------------------------
extern "C" void kernel_launch(void* const* d_in, const int* in_sizes, int n_in,
                              void* d_out, int out_size)
{
    const float* f0 = (const float*)d_in[0];
    const float* f1 = (const float*)d_in[1];
    const float* f2 = (const float*)d_in[2];
    const float* f3 = (const float*)d_in[3];
    const float* f4 = (const float*)d_in[4];
    const float* w_pre  = (const float*)d_in[5];
    const float* b_pre  = (const float*)d_in[6];
    const float* w_proj = (const float*)d_in[7];
    const float* b_proj = (const float*)d_in[8];

    float* out = (float*)d_out;
    const int SL = NB * NA;          // 1571328
    const int SI = NB * KSEL;        // 2400
    const int SF = NB * KSEL * 256;  // 614400

    float *olg = 0, *oid = 0, *ofe = 0;
    if (out_size == SL + SI + SF)      { olg = out; oid = out + SL; ofe = out + SL + SI; }
    else if (out_size == SF)           { ofe = out; }
    else if (out_size == SL)           { olg = out; }
    else if (out_size == SI)           { oid = out; }
    else if (out_size == SI + SF)      { oid = out; ofe = out + SI; }
    else if (out_size == SL + SF)      { olg = out; ofe = out + SL; }
    else if (out_size == SL + SI)      { olg = out; oid = out + SL; }
    else                               { olg = out; oid = out + SL; ofe = out + SL + SI; }

    cudaFuncSetAttribute(k_logits, cudaFuncAttributeMaxDynamicSharedMemorySize, SM_TOT);

    k_wprep<<<256, 256>>>(w_pre);
    k_logits<<<NB * TPI, 256, SM_TOT>>>(f0, f1, f2, f3, f4, b_pre, w_proj, b_proj, olg);
    k_hist1<<<dim3(24, NB), 256>>>();
    k_scan<<<NB, 256>>>(0);
    k_hist2<<<dim3(24, NB), 256>>>();
    k_scan<<<NB, 256>>>(1);
    k_collect<<<dim3(24, NB), 256>>>();
    k_exact<<<NB * 256, 256>>>(f0, f1, f2, f3, f4, w_pre, b_pre, w_proj, b_proj);
    k_final<<<NB, 1024>>>(oid);
    if (ofe) k_gather<<<NB * KSEL, 256>>>(f0, f1, f2, f3, f4, ofe);
}

// round 16
// speedup vs baseline: 1.0194x; 1.0194x over previous
#include <cuda_runtime.h>
#include <cuda_bf16.h>
#include <math.h>

typedef unsigned int u32;
typedef unsigned long long u64;

#define NA   196416   // anchors per image
#define NP   21824    // positions per image
#define KSEL 300
#define NB   8
#define CMAX 2048     // candidate cap per image
#define GEX  8        // candidates per k_exact block
#define TPI  171      // GEMM tiles per image (170 x 128 pos + 1 x 64 pos)

__device__ u32 g_keys[NB * NA];        // approx sortable logit keys
__device__ u32 g_hist1[NB * 2048];
__device__ u32 g_hist2[NB * 2048];
__device__ u32 g_sel1[NB * 2];
__device__ u32 g_sel2[NB * 2];
__device__ u32 g_ccnt[NB];
__device__ u32 g_cand[NB * CMAX];      // candidate anchor indices (within image)
__device__ u64 g_eres[NB * CMAX];      // recomputed composite keys (key<<32 | ~idx)
__device__ int g_stage[NB * KSEL];
__device__ uint4 g_wbf4[65536 / 8];    // W bf16 [256 o][256 k]

__device__ __forceinline__ u32 fkey(float v) {
    u32 s = __float_as_uint(v);
    return (s & 0x80000000u) ? ~s : (s | 0x80000000u);
}
__device__ __forceinline__ u32 smem_u32(const void* p) {
    u32 a;
    asm("{ .reg .u64 t; cvta.to.shared.u64 t, %1; cvt.u32.u64 %0, t; }" : "=r"(a) : "l"(p));
    return a;
}
__device__ __forceinline__ void ldsm_x4(u32 addr, u32* r) {
    asm volatile("ldmatrix.sync.aligned.m8n8.x4.shared.b16 {%0,%1,%2,%3}, [%4];"
        : "=r"(r[0]), "=r"(r[1]), "=r"(r[2]), "=r"(r[3]) : "r"(addr));
}
__device__ __forceinline__ void ldsm_x4t(u32 addr, u32* r) {
    asm volatile("ldmatrix.sync.aligned.m8n8.x4.trans.shared.b16 {%0,%1,%2,%3}, [%4];"
        : "=r"(r[0]), "=r"(r[1]), "=r"(r[2]), "=r"(r[3]) : "r"(addr));
}
__device__ __forceinline__ void mma_bf16(float* d, const u32* a, const u32* b) {
    asm volatile(
        "mma.sync.aligned.m16n8k16.row.col.f32.bf16.bf16.f32 "
        "{%0,%1,%2,%3}, {%4,%5,%6,%7}, {%8,%9}, {%0,%1,%2,%3};"
        : "+f"(d[0]), "+f"(d[1]), "+f"(d[2]), "+f"(d[3])
        : "r"(a[0]), "r"(a[1]), "r"(a[2]), "r"(a[3]), "r"(b[0]), "r"(b[1]));
}
__device__ __forceinline__ void cp16(u32 dst, const void* src) {
    asm volatile("cp.async.cg.shared.global [%0], [%1], 16;" :: "r"(dst), "l"(src) : "memory");
}
#define CP_COMMIT() asm volatile("cp.async.commit_group;" ::: "memory")
#define CP_WAIT0()  asm volatile("cp.async.wait_group 0;" ::: "memory")

// ---------------------------------------------------------------------------
// Prep: W -> bf16 [256 o][256 k]
// ---------------------------------------------------------------------------
__global__ void __launch_bounds__(256) k_wprep(const float* __restrict__ w_pre)
{
    const int i = blockIdx.x * 256 + threadIdx.x;
    ((__nv_bfloat16*)g_wbf4)[i] = __float2bfloat16(w_pre[i]);
}

// ---------------------------------------------------------------------------
// K1: single-product bf16 mma.sync GEMM 256x256 conv + ReLU + fp32 proj.
// Block: M=256 x N=128 positions, 8 warps (4 m x 2 n), K chunks of 64, dbuf.
// smem: W [buf][256 o][144B rows], X [buf][64 k][272B rows].
// ---------------------------------------------------------------------------
#define SW_BUF  36864
#define SX_BASE 73728
#define SX_BUF  17408
#define SMO_WPROJ 139264
#define SMO_BPRE  148480
#define SMO_BPROJ 149504
#define SM_TOT    149568

__global__ void __launch_bounds__(256, 1) k_logits(
    const float* __restrict__ f0, const float* __restrict__ f1,
    const float* __restrict__ f2, const float* __restrict__ f3,
    const float* __restrict__ f4,
    const float* __restrict__ b_pre_g,
    const float* __restrict__ w_proj_g, const float* __restrict__ b_proj_g,
    float* __restrict__ out_lg)
{
    extern __shared__ unsigned char sm[];
    const u32 smb = smem_u32(sm);
    float* pre_s   = (float*)sm;                    // epilogue reuse [256 o][136]
    float* wproj_s = (float*)(sm + SMO_WPROJ);
    float* bpre_s  = (float*)(sm + SMO_BPRE);
    float* bproj_s = (float*)(sm + SMO_BPROJ);

    const int tid = threadIdx.x;
    const int wid = tid >> 5;
    const int lane = tid & 31;
    const int mw = wid >> 1;     // 0..3 (M group of 64)
    const int nw = wid & 1;      // 0..1 (N group of 64)

    // fold topk zeroing into spare blocks
    if (blockIdx.x < 64)        g_hist1[blockIdx.x * 256 + tid] = 0;
    else if (blockIdx.x < 128)  g_hist2[(blockIdx.x - 64) * 256 + tid] = 0;
    else if (blockIdx.x == 128 && tid < NB) g_ccnt[tid] = 0;

    for (int i = tid; i < 2304; i += 256) wproj_s[i] = w_proj_g[i];
    bpre_s[tid] = b_pre_g[tid];
    if (tid < 9) bproj_s[tid] = b_proj_g[tid];

    // block decode
    const int img = blockIdx.x / TPI;
    const int t = blockIdx.x - img * TPI;
    const float* F; int HW, posoff, pt, Ntile;
    if (t < 128)      { F = f0; HW = 16384; posoff = 0;     pt = t;       Ntile = 128; }
    else if (t < 160) { F = f1; HW = 4096;  posoff = 16384; pt = t - 128; Ntile = 128; }
    else if (t < 168) { F = f2; HW = 1024;  posoff = 20480; pt = t - 160; Ntile = 128; }
    else if (t < 170) { F = f3; HW = 256;   posoff = 21504; pt = t - 168; Ntile = 128; }
    else              { F = f4; HW = 64;    posoff = 21760; pt = 0;       Ntile = 64;  }
    const float* Xg = F + (size_t)img * 256 * HW + (size_t)pt * 128;
    const int pmask = (Ntile == 128) ? 127 : 63;

    const __nv_bfloat16* gW = (const __nv_bfloat16*)g_wbf4;

    // per-lane ldmatrix address components
    const u32 aoff = (u32)((mw * 64 + (lane & 15)) * 144 + ((lane >> 4) << 4));
    const u32 boff = (u32)(((lane & 7) + (lane & 8)) * 272 + ((nw * 64 + ((lane >> 4) << 3)) << 1));

    // X staging: thread -> k row (tid>>2: 0..63), p block (tid&3)*32
    const int xk = tid >> 2;
    const int xp4 = (tid & 3) * 32;

    float acc[4][8][4];
    #pragma unroll
    for (int mi = 0; mi < 4; mi++)
        #pragma unroll
        for (int nf = 0; nf < 8; nf++)
            #pragma unroll
            for (int q = 0; q < 4; q++) acc[mi][nf][q] = 0.f;

    float4 xv[8];

    auto issueW = [&](int c, int buf) {
        #pragma unroll
        for (int i = 0; i < 8; i++) {
            const int idx = tid + i * 256;
            const int o = idx >> 3, j = idx & 7;
            const u32 dst = smb + (u32)(buf * SW_BUF + o * 144 + j * 16);
            cp16(dst, gW + o * 256 + c * 64 + j * 8);
        }
        CP_COMMIT();
    };
    auto loadX = [&](int c) {
        #pragma unroll
        for (int i = 0; i < 8; i++) {
            const int p = (xp4 + 4 * i) & pmask;
            xv[i] = *(const float4*)(Xg + (size_t)(c * 64 + xk) * HW + p);
        }
    };
    auto stsX = [&](int buf) {
        const u32 rb = smb + (u32)(SX_BASE + buf * SX_BUF + xk * 272);
        #pragma unroll
        for (int i = 0; i < 8; i++) {
            const float4 v = xv[i];
            const u32 w0 = ((u32)__bfloat16_as_ushort(__float2bfloat16(v.y)) << 16)
                         | (u32)__bfloat16_as_ushort(__float2bfloat16(v.x));
            const u32 w1 = ((u32)__bfloat16_as_ushort(__float2bfloat16(v.w)) << 16)
                         | (u32)__bfloat16_as_ushort(__float2bfloat16(v.z));
            asm volatile("st.shared.v2.u32 [%0], {%1, %2};"
                         :: "r"(rb + (u32)((xp4 + 4 * i) * 2)), "r"(w0), "r"(w1) : "memory");
        }
    };

    issueW(0, 0);
    loadX(0);
    CP_WAIT0();
    __syncthreads();
    stsX(0);
    __syncthreads();

    for (int c = 0; c < 4; c++) {
        const int cur = c & 1, nxt = cur ^ 1;
        if (c < 3) { issueW(c + 1, nxt); loadX(c + 1); }

        #pragma unroll
        for (int k16 = 0; k16 < 4; k16++) {
            const u32 abase = smb + (u32)(cur * SW_BUF) + aoff + (u32)(k16 * 32);
            const u32 bbase = smb + (u32)(SX_BASE + cur * SX_BUF + k16 * 4352) + boff;
            u32 A[4][4], B[4][4];
            #pragma unroll
            for (int mi = 0; mi < 4; mi++) ldsm_x4(abase + mi * 2304, A[mi]);
            #pragma unroll
            for (int q = 0; q < 4; q++) ldsm_x4t(bbase + q * 32, B[q]);
            #pragma unroll
            for (int mi = 0; mi < 4; mi++)
                #pragma unroll
                for (int q = 0; q < 4; q++) {
                    mma_bf16(acc[mi][2 * q], A[mi], &B[q][0]);
                    mma_bf16(acc[mi][2 * q + 1], A[mi], &B[q][2]);
                }
        }

        if (c < 3) {
            CP_WAIT0();
            __syncthreads();
            stsX(nxt);
            __syncthreads();
        }
    }

    // epilogue: relu(acc + b_pre) -> pre_s[o][136]
    __syncthreads();
    #pragma unroll
    for (int mi = 0; mi < 4; mi++) {
        #pragma unroll
        for (int h = 0; h < 2; h++) {
            const int o = mw * 64 + mi * 16 + (lane >> 2) + 8 * h;
            const float bb = bpre_s[o];
            #pragma unroll
            for (int nf = 0; nf < 8; nf++) {
                const int n = nw * 64 + nf * 8 + 2 * (lane & 3);
                float2 v;
                v.x = fmaxf(acc[mi][nf][2 * h] + bb, 0.f);
                v.y = fmaxf(acc[mi][nf][2 * h + 1] + bb, 0.f);
                *(float2*)(pre_s + o * 136 + n) = v;
            }
        }
    }
    __syncthreads();

    // projection: thread (p, grp): grp0 -> a 0..4, grp1 -> a 5..8
    {
        const int p = tid & 127;
        const int grp = tid >> 7;
        if (p < Ntile) {
            const int a0 = grp ? 5 : 0;
            const int na = grp ? 4 : 5;
            float pa[5] = {0.f, 0.f, 0.f, 0.f, 0.f};
            #pragma unroll 4
            for (int o = 0; o < 256; o++) {
                const float v = pre_s[o * 136 + p];
                #pragma unroll
                for (int q = 0; q < 5; q++)
                    if (q < na) pa[q] = fmaf(wproj_s[(a0 + q) * 256 + o], v, pa[q]);
            }
            const size_t obase = (size_t)img * NA;
            const int ab = (posoff + pt * 128 + p) * 9;
            for (int q = 0; q < na; q++) {
                const float val = pa[q] + bproj_s[a0 + q];
                const int anch = ab + a0 + q;
                if (out_lg) out_lg[obase + anch] = val;
                g_keys[obase + anch] = fkey(val);
            }
        }
    }
}

// ---------------------------------------------------------------------------
// Top-k radix passes. 48 chunks x 1023 uint4 per image (48*1023 = 49104 = NA/4).
// ---------------------------------------------------------------------------
__device__ __forceinline__ void hadd(u32* hist, u32 bin, bool valid, int lane) {
    u32 key = valid ? bin : 0xFFFFFFFFu;
    u32 m = __match_any_sync(0xFFFFFFFFu, key);
    if (valid && lane == (__ffs(m) - 1)) atomicAdd(&hist[bin], __popc(m));
}

__global__ void __launch_bounds__(256) k_hist1()
{
    __shared__ u32 hist[2048];
    const int t = threadIdx.x, img = blockIdx.y, chunk = blockIdx.x;
    const int lane = t & 31;
    for (int i = t; i < 2048; i += 256) hist[i] = 0;
    __syncthreads();
    const uint4* src = (const uint4*)(g_keys + img * NA) + chunk * 1023;
    for (int i = t; i < 1024; i += 256) {
        const bool v = i < 1023;
        uint4 x = v ? src[i] : make_uint4(0, 0, 0, 0);
        hadd(hist, x.x >> 21, v, lane);
        hadd(hist, x.y >> 21, v, lane);
        hadd(hist, x.z >> 21, v, lane);
        hadd(hist, x.w >> 21, v, lane);
    }
    __syncthreads();
    for (int i = t; i < 2048; i += 256)
        if (hist[i]) atomicAdd(&g_hist1[img * 2048 + i], hist[i]);
}

__global__ void __launch_bounds__(256) k_hist2()
{
    __shared__ u32 hist[2048];
    const int t = threadIdx.x, img = blockIdx.y, chunk = blockIdx.x;
    const int lane = t & 31;
    const u32 B1 = g_sel1[img * 2];
    for (int i = t; i < 2048; i += 256) hist[i] = 0;
    __syncthreads();
    const uint4* src = (const uint4*)(g_keys + img * NA) + chunk * 1023;
    for (int i = t; i < 1024; i += 256) {
        const bool v = i < 1023;
        uint4 x = v ? src[i] : make_uint4(0, 0, 0, 0);
        hadd(hist, (x.x >> 10) & 2047u, v && ((x.x >> 21) == B1), lane);
        hadd(hist, (x.y >> 10) & 2047u, v && ((x.y >> 21) == B1), lane);
        hadd(hist, (x.z >> 10) & 2047u, v && ((x.z >> 21) == B1), lane);
        hadd(hist, (x.w >> 10) & 2047u, v && ((x.w >> 21) == B1), lane);
    }
    __syncthreads();
    for (int i = t; i < 2048; i += 256)
        if (hist[i]) atomicAdd(&g_hist2[img * 2048 + i], hist[i]);
}

__global__ void __launch_bounds__(256) k_scan(int pass)
{
    __shared__ u32 h[2048];
    __shared__ u32 part[256], sc[256];
    __shared__ u32 res[2];
    const int t = threadIdx.x, img = blockIdx.x;
    const u32* H = (pass ? g_hist2 : g_hist1) + img * 2048;
    for (int i = t; i < 2048; i += 256) h[i] = H[i];
    __syncthreads();
    const u32 base = pass ? g_sel1[img * 2 + 1] : 0u;
    const u32 need = KSEL - base;
    u32 loc = 0;
    #pragma unroll
    for (int q = 0; q < 8; q++) loc += h[2047 - (t * 8 + q)];
    part[t] = loc; sc[t] = loc;
    __syncthreads();
    for (int off = 1; off < 256; off <<= 1) {
        u32 v = (t >= off) ? sc[t - off] : 0u;
        __syncthreads();
        sc[t] += v;
        __syncthreads();
    }
    const u32 A = sc[t] - part[t];
    if (A < need && A + part[t] >= need) {
        u32 cum = A;
        #pragma unroll
        for (int q = 0; q < 8; q++) {
            const u32 bin = 2047 - (t * 8 + q);
            const u32 hv = h[bin];
            if (cum + hv >= need) { res[0] = bin; res[1] = base + cum; break; }
            cum += hv;
        }
    }
    __syncthreads();
    if (t == 0) {
        u32* outsel = (pass ? g_sel2 : g_sel1) + img * 2;
        outsel[0] = res[0]; outsel[1] = res[1];
    }
}

// collect candidates: approx top-22 bits >= threshold bin - 64 (noise margin)
__global__ void __launch_bounds__(256) k_collect()
{
    const int t = threadIdx.x, img = blockIdx.y, chunk = blockIdx.x;
    const u32 hi22 = (g_sel1[img * 2] << 11) | g_sel2[img * 2];
    const u32 lo = (hi22 > 64) ? (hi22 - 64) : 0u;
    const uint4* src = (const uint4*)(g_keys + img * NA) + chunk * 1023;
    u32* cand = g_cand + (size_t)img * CMAX;
    for (int i = t; i < 1023; i += 256) {
        uint4 x = src[i];
        const u32 ib = (u32)((chunk * 1023 + i) * 4);
        u32 xs4[4] = {x.x, x.y, x.z, x.w};
        #pragma unroll
        for (int c = 0; c < 4; c++) {
            if ((xs4[c] >> 10) >= lo) {
                const u32 slot = atomicAdd(&g_ccnt[img], 1u);
                if (slot < CMAX) cand[slot] = ib + c;
            }
        }
    }
}

// ---------------------------------------------------------------------------
// k_exact: fp32 recompute replicating R4's JAX-matching arithmetic.
// ---------------------------------------------------------------------------
__global__ void __launch_bounds__(256) k_exact(
    const float* __restrict__ f0, const float* __restrict__ f1,
    const float* __restrict__ f2, const float* __restrict__ f3,
    const float* __restrict__ f4,
    const float* __restrict__ w_pre, const float* __restrict__ b_pre,
    const float* __restrict__ w_proj, const float* __restrict__ b_proj)
{
    __shared__ float xs[GEX][260];       // x channels per candidate; reused as pre
    __shared__ float wc[256][33];        // W chunk [o][32k], padded
    __shared__ int s_idx[GEX];

    const int tid = threadIdx.x;
    const int img = blockIdx.x >> 8;           // / 256
    const int grp = blockIdx.x & 255;
    u32 cnt = g_ccnt[img]; if (cnt > CMAX) cnt = CMAX;
    const int base = grp * GEX;
    u64* outk = g_eres + (size_t)img * CMAX;

    if ((u32)base >= cnt) {
        if (tid < GEX) outk[base + tid] = 0ull;
        return;
    }
    if (tid < GEX)
        s_idx[tid] = ((u32)(base + tid) < cnt) ? (int)g_cand[(size_t)img * CMAX + base + tid] : -1;
    __syncthreads();

    #pragma unroll 1
    for (int g = 0; g < GEX; g++) {
        const int idx = s_idx[g];
        float v = 0.f;
        if (idx >= 0) {
            const int pos = idx / 9;
            const float* F; int HW, off;
            if (pos < 16384)      { F = f0; HW = 16384; off = 0; }
            else if (pos < 20480) { F = f1; HW = 4096;  off = 16384; }
            else if (pos < 21504) { F = f2; HW = 1024;  off = 20480; }
            else if (pos < 21760) { F = f3; HW = 256;   off = 21504; }
            else                  { F = f4; HW = 64;    off = 21760; }
            v = F[((size_t)img * 256 + tid) * (size_t)HW + (pos - off)];
        }
        xs[g][tid] = v;
    }

    float acc_e[GEX], acc_o[GEX];
    #pragma unroll
    for (int g = 0; g < GEX; g++) { acc_e[g] = 0.f; acc_o[g] = 0.f; }

    for (int kc = 0; kc < 8; kc++) {
        __syncthreads();
        for (int i = tid; i < 8192; i += 256) {
            const int o = i >> 5, k = i & 31;
            wc[o][k] = w_pre[o * 256 + kc * 32 + k];
        }
        __syncthreads();
        const int kb = kc * 32;
        #pragma unroll 4
        for (int kk = 0; kk < 32; kk += 2) {
            const float we = wc[tid][kk];
            const float wo = wc[tid][kk + 1];
            #pragma unroll
            for (int g = 0; g < GEX; g++) {
                acc_e[g] = fmaf(we, xs[g][kb + kk], acc_e[g]);
                acc_o[g] = fmaf(wo, xs[g][kb + kk + 1], acc_o[g]);
            }
        }
    }
    __syncthreads();

    const float bb = b_pre[tid];
    #pragma unroll
    for (int g = 0; g < GEX; g++)
        xs[g][tid] = fmaxf(acc_e[g] + acc_o[g] + bb, 0.f);
    __syncthreads();

    if (tid < GEX) {
        const int idx = s_idx[tid];
        if (idx >= 0) {
            const int a = idx - (idx / 9) * 9;
            const float* wp = w_proj + a * 256;
            float lg = 0.f;
            #pragma unroll 8
            for (int o = 0; o < 256; o++)
                lg = fmaf(wp[o], xs[tid][o], lg);
            const float val = lg + b_proj[a];
            outk[base + tid] = ((u64)fkey(val) << 32) | (u64)(0xFFFFFFFFu - (u32)idx);
        } else {
            outk[base + tid] = 0ull;
        }
    }
}

// ---------------------------------------------------------------------------
// k_final: sort up to 2048 keys desc (key desc, idx asc), emit top-300
// ---------------------------------------------------------------------------
__global__ void __launch_bounds__(1024) k_final(float* __restrict__ out_ids)
{
    __shared__ u64 keys[CMAX];
    const int t = threadIdx.x, img = blockIdx.x;
    u32 cnt = g_ccnt[img];
    if (cnt > CMAX) cnt = CMAX;
    u32 m = 512; while (m < cnt) m <<= 1;
    for (u32 i = t; i < m; i += 1024)
        keys[i] = (i < cnt) ? g_eres[(size_t)img * CMAX + i] : 0ull;
    __syncthreads();
    for (u32 k = 2; k <= m; k <<= 1)
        for (u32 j = k >> 1; j > 0; j >>= 1) {
            for (u32 i = t; i < m; i += 1024) {
                const u32 ix = i ^ j;
                if (ix > i) {
                    const u64 a = keys[i], c = keys[ix];
                    const bool down = ((i & k) == 0);
                    if ((a < c) == down) { keys[i] = c; keys[ix] = a; }
                }
            }
            __syncthreads();
        }
    if (t < KSEL) {
        const u32 idx = 0xFFFFFFFFu - (u32)keys[t];
        const int sel = img * NA + (int)idx;
        g_stage[img * KSEL + t] = sel;
        if (out_ids) out_ids[img * KSEL + t] = (float)sel;
    }
}

// ---------------------------------------------------------------------------
// K3: gather selected features [2400, 256]
// ---------------------------------------------------------------------------
__global__ void __launch_bounds__(256) k_gather(
    const float* __restrict__ f0, const float* __restrict__ f1,
    const float* __restrict__ f2, const float* __restrict__ f3,
    const float* __restrict__ f4, float* __restrict__ out_f)
{
    const int j = blockIdx.x;
    const int id = g_stage[j];
    const int b = id / NA;
    const int p = id / 9 - b * NP;
    const float* F; int HW, off;
    if (p < 16384)      { F = f0; HW = 16384; off = 0; }
    else if (p < 20480) { F = f1; HW = 4096;  off = 16384; }
    else if (p < 21504) { F = f2; HW = 1024;  off = 20480; }
    else if (p < 21760) { F = f3; HW = 256;   off = 21504; }
    else                { F = f4; HW = 64;    off = 21760; }
    const int pos = p - off;
    const int c = threadIdx.x;
    out_f[(size_t)j * 256 + c] = F[((size_t)b * 256 + c) * (size_t)HW + pos];
}

// ---------------------------------------------------------------------------
extern "C" void kernel_launch(void* const* d_in, const int* in_sizes, int n_in,
                              void* d_out, int out_size)
{
    const float* f0 = (const float*)d_in[0];
    const float* f1 = (const float*)d_in[1];
    const float* f2 = (const float*)d_in[2];
    const float* f3 = (const float*)d_in[3];
    const float* f4 = (const float*)d_in[4];
    const float* w_pre  = (const float*)d_in[5];
    const float* b_pre  = (const float*)d_in[6];
    const float* w_proj = (const float*)d_in[7];
    const float* b_proj = (const float*)d_in[8];

    float* out = (float*)d_out;
    const int SL = NB * NA;          // 1571328
    const int SI = NB * KSEL;        // 2400
    const int SF = NB * KSEL * 256;  // 614400

    float *olg = 0, *oid = 0, *ofe = 0;
    if (out_size == SL + SI + SF)      { olg = out; oid = out + SL; ofe = out + SL + SI; }
    else if (out_size == SF)           { ofe = out; }
    else if (out_size == SL)           { olg = out; }
    else if (out_size == SI)           { oid = out; }
    else if (out_size == SI + SF)      { oid = out; ofe = out + SI; }
    else if (out_size == SL + SF)      { olg = out; ofe = out + SL; }
    else if (out_size == SL + SI)      { olg = out; oid = out + SL; }
    else                               { olg = out; oid = out + SL; ofe = out + SL + SI; }

    cudaFuncSetAttribute(k_logits, cudaFuncAttributeMaxDynamicSharedMemorySize, SM_TOT);

    k_wprep<<<256, 256>>>(w_pre);
    k_logits<<<NB * TPI, 256, SM_TOT>>>(f0, f1, f2, f3, f4, b_pre, w_proj, b_proj, olg);
    k_hist1<<<dim3(48, NB), 256>>>();
    k_scan<<<NB, 256>>>(0);
    k_hist2<<<dim3(48, NB), 256>>>();
    k_scan<<<NB, 256>>>(1);
    k_collect<<<dim3(48, NB), 256>>>();
    k_exact<<<NB * 256, 256>>>(f0, f1, f2, f3, f4, w_pre, b_pre, w_proj, b_proj);
    k_final<<<NB, 1024>>>(oid);
    if (ofe) k_gather<<<NB * KSEL, 256>>>(f0, f1, f2, f3, f4, ofe);
}